// round 14
// baseline (speedup 1.0000x reference)
#include <cuda_runtime.h>
#include <cstdint>
#include <float.h>

#define BB 8
#define NN 2048
#define CC 128
#define KK 9
#define CO 256
#define NROWS (BB*NN)        // 16384

// ---- scratch (device globals: allocation-free contract) ----
__device__ float  g_sq[NROWS];
__device__ int    g_nn[NROWS*KK];
__device__ float  g_cv[(size_t)NROWS*2*KK];  // per-half top-9 values
__device__ int    g_ci[(size_t)NROWS*2*KK];  // per-half top-9 indices
__device__ float  g_M2T[CC*512];
__device__ float  g_PQ[(size_t)NROWS*512];
__device__ float  g_Hsel[(size_t)NROWS*CO];
__device__ float  g_part[512*512];
__device__ float  g_scale[CO];
__device__ float  g_shift[CO];
__device__ float  g_XT[(size_t)NROWS*CC];    // x transposed [b][n][c], fp32
__device__ float2 g_XT2[(size_t)NROWS*CC];   // x transposed [b][n][c], (hi, lo)

// warp-level tf32 MMA (sm_80+ generic PTX)
#define MMA_TF32(c0,c1,c2,c3, a0,a1,a2,a3, b0,b1)                          \
    asm volatile("mma.sync.aligned.m16n8k8.row.col.f32.tf32.tf32.f32 "     \
        "{%0,%1,%2,%3}, {%4,%5,%6,%7}, {%8,%9}, {%0,%1,%2,%3};"            \
        : "+f"(c0), "+f"(c1), "+f"(c2), "+f"(c3)                           \
        : "r"(a0), "r"(a1), "r"(a2), "r"(a3), "r"(b0), "r"(b1))

// cheap exact split: hi = truncate-to-tf32 (mask), lo = v - hi (exact fp32).
#define SPLIT(u, hi, lo)                                                   \
    do { hi = (u) & 0xFFFFE000u;                                           \
         lo = __float_as_uint(__uint_as_float(u) - __uint_as_float(hi)); } while (0)

// ------------------------------------------------------------------
// prep: M2T = [[W1-W2];[W2]] transposed to [c][o']
// ------------------------------------------------------------------
__global__ void prep_k(const float* __restrict__ W) {
    int i = blockIdx.x*256 + threadIdx.x;
    if (i >= 512*CC) return;
    int c = i >> 9, o = i & 511;
    float v;
    if (o < CO) v = W[o*256 + c] - W[o*256 + 128 + c];
    else        v = W[(o-CO)*256 + 128 + c];
    g_M2T[c*512 + o] = v;
}

// ------------------------------------------------------------------
// sq: per-point squared norm (x layout [b][c][n])
// ------------------------------------------------------------------
__global__ void sq_k(const float* __restrict__ x) {
    int t = blockIdx.x*256 + threadIdx.x;
    int b = t >> 11, n = t & (NN-1);
    const float* xb = x + (size_t)b*CC*NN + n;
    float s = 0.f;
    #pragma unroll 8
    for (int c = 0; c < CC; c++) { float v = xb[(size_t)c*NN]; s = fmaf(v, v, s); }
    g_sq[t] = s;
}

// ------------------------------------------------------------------
// xt: transpose x [b][c][n] -> XT (fp32) and XT2 ((hi,lo) float2)
// ------------------------------------------------------------------
__global__ void xt_k(const float* __restrict__ x) {
    __shared__ float t[32][33];
    int b = blockIdx.z, n0 = blockIdx.x*32, c0 = blockIdx.y*32;
    int tx = threadIdx.x, ty = threadIdx.y;   // 32 x 8
    #pragma unroll
    for (int i = 0; i < 4; i++)
        t[ty + i*8][tx] = x[((size_t)(b*CC + c0 + ty + i*8))*NN + n0 + tx];
    __syncthreads();
    #pragma unroll
    for (int i = 0; i < 4; i++) {
        int n = n0 + ty + i*8;
        float v = t[tx][ty + i*8];
        uint32_t u = __float_as_uint(v);
        uint32_t hu = u & 0xFFFFE000u;
        float hi = __uint_as_float(hu);
        size_t idx = ((size_t)(b*NN + n))*CC + c0 + tx;
        g_XT[idx]  = v;
        g_XT2[idx] = make_float2(hi, v - hi);
    }
}

// ------------------------------------------------------------------
// gram_mma v10: interleaved (hi,lo) A, fp32 B + register split.
// CTA = 64-row strip x 1024 cols (half). Grid (32, 2, 8) = 512 CTAs
// -> 2 CTAs/SM (101KB smem), 16 warps/SM.
// 256 threads = 8 warps (2m x 4n), warp tile 32x16 over 64x64 tiles.
// Per warp k-step: 8 LDS.64 (A, no split) + 4 LDS.32 + 8 ALU (B) + 12 MMA.
// ------------------------------------------------------------------
#define PADA 132   // float2 units; row stride 264 words = 8 mod 32 -> conflict-free
#define PADB 132
#define SDP 65

__global__ __launch_bounds__(256, 2) void gram_mma_k() {
    extern __shared__ float sm[];
    float2* sA2 = (float2*)sm;               // 64 x 132 float2 (67.6KB)
    float*  sB  = sm + 64*PADA*2;            // 64 x 132 fp32   (33.8KB)
    float*  sD  = sB;                        // overlay: 64*65 <= 64*132
    __shared__ float sSq[64];

    const int tid  = threadIdx.x;
    const int warp = tid >> 5, lane = tid & 31;
    const int qr = lane >> 2, qc = lane & 3;
    const int wm = (warp & 1) * 32;    // row base within 64-strip (2 m-groups)
    const int wn = (warp >> 1) * 16;   // col base within 64-tile  (4 n-groups)
    const int half = blockIdx.y;
    const int b = blockIdx.z, n0 = blockIdx.x*64;

    // topk scan mapping: 4 threads per row, 16 cols each
    const int srow = tid & 63;
    const int sq4  = tid >> 6;

    // load A strip (rows n0..n0+63): 64x128 float2
    {
        const float4* src = (const float4*)(g_XT2 + (size_t)(b*NN + n0)*CC);
        #pragma unroll
        for (int it = 0; it < 16; it++) {
            int g = it*256 + tid;
            int row = g >> 6, c4 = g & 63;       // c4 = pair-of-float2 index
            *(float4*)&sA2[row*PADA + c4*2] = src[g];
        }
    }

    float tv[9]; int ti[9];            // ONE top-9 list per thread
    #pragma unroll
    for (int q = 0; q < KK; q++) { tv[q] = FLT_MAX; ti[q] = 0x7FFFFFFF; }

    for (int mt = 0; mt < 16; mt++) {
        const int m0 = (half*16 + mt)*64;
        __syncthreads();   // prev scan done; B/sD region reusable
        {
            const float4* src = (const float4*)(g_XT + (size_t)(b*NN + m0)*CC);
            #pragma unroll
            for (int it = 0; it < 8; it++) {
                int g = it*256 + tid;
                int row = g >> 5, c4 = (g & 31) * 4;
                *(float4*)&sB[row*PADB + c4] = src[g];
            }
            if (tid < 64) sSq[tid] = g_sq[b*NN + m0 + tid];
        }
        __syncthreads();

        float acc[2][2][4];
        #pragma unroll
        for (int mi = 0; mi < 2; mi++)
            #pragma unroll
            for (int nj = 0; nj < 2; nj++)
                #pragma unroll
                for (int r = 0; r < 4; r++) acc[mi][nj][r] = 0.f;

        #pragma unroll
        for (int ks = 0; ks < 16; ks++) {
            const int k0 = ks*8;
            uint32_t ah[2][4], al[2][4], bh[2][2], bl[2][2];
            #pragma unroll
            for (int mi = 0; mi < 2; mi++) {
                const int r0 = wm + 16*mi + qr;
                uint2 e0 = *(const uint2*)&sA2[r0*PADA + k0 + qc];
                uint2 e1 = *(const uint2*)&sA2[(r0+8)*PADA + k0 + qc];
                uint2 e2 = *(const uint2*)&sA2[r0*PADA + k0 + qc + 4];
                uint2 e3 = *(const uint2*)&sA2[(r0+8)*PADA + k0 + qc + 4];
                ah[mi][0] = e0.x; al[mi][0] = e0.y;
                ah[mi][1] = e1.x; al[mi][1] = e1.y;
                ah[mi][2] = e2.x; al[mi][2] = e2.y;
                ah[mi][3] = e3.x; al[mi][3] = e3.y;
            }
            #pragma unroll
            for (int nj = 0; nj < 2; nj++) {
                const uint32_t* p = (const uint32_t*)(sB + (wn + 8*nj + qr)*PADB + k0 + qc);
                uint32_t u0 = p[0], u1 = p[4];
                SPLIT(u0, bh[nj][0], bl[nj][0]);
                SPLIT(u1, bh[nj][1], bl[nj][1]);
            }
            #pragma unroll
            for (int mi = 0; mi < 2; mi++)
                #pragma unroll
                for (int nj = 0; nj < 2; nj++) {
                    MMA_TF32(acc[mi][nj][0], acc[mi][nj][1], acc[mi][nj][2], acc[mi][nj][3],
                             ah[mi][0], ah[mi][1], ah[mi][2], ah[mi][3], bh[nj][0], bh[nj][1]);
                    MMA_TF32(acc[mi][nj][0], acc[mi][nj][1], acc[mi][nj][2], acc[mi][nj][3],
                             al[mi][0], al[mi][1], al[mi][2], al[mi][3], bh[nj][0], bh[nj][1]);
                    MMA_TF32(acc[mi][nj][0], acc[mi][nj][1], acc[mi][nj][2], acc[mi][nj][3],
                             ah[mi][0], ah[mi][1], ah[mi][2], ah[mi][3], bl[nj][0], bl[nj][1]);
                }
        }

        // stage d-tile (all warps done reading B -> overlay safe)
        __syncthreads();
        #pragma unroll
        for (int mi = 0; mi < 2; mi++)
            #pragma unroll
            for (int nj = 0; nj < 2; nj++)
                #pragma unroll
                for (int r = 0; r < 4; r++) {
                    const int row = wm + 16*mi + 8*(r >> 1) + qr;
                    const int col = wn + 8*nj + 2*qc + (r & 1);
                    sD[row*SDP + col] = sSq[col] - 2.f*acc[mi][nj][r];
                }
        __syncthreads();

        // top-9 scan: thread (srow, sq4) scans 16 cols, ascending m
        {
            const float* dr = sD + srow*SDP + sq4*16;
            const int mb = m0 + sq4*16;
            #pragma unroll 8
            for (int j = 0; j < 16; j++) {
                float d = dr[j];
                if (d < tv[8]) {
                    tv[8] = d; ti[8] = mb + j;
                    #pragma unroll
                    for (int q = 8; q > 0; q--) {
                        if (tv[q] < tv[q-1]) {
                            float fv = tv[q]; tv[q] = tv[q-1]; tv[q-1] = fv;
                            int iv = ti[q];  ti[q] = ti[q-1]; ti[q-1] = iv;
                        }
                    }
                }
            }
        }
    }

    // in-CTA merge: 4 threads per row x 9 = 36 -> 9 for this half
    __syncthreads();
    float* mv  = sm;                   // [64][36] values
    int*   mi_ = (int*)(sm + 64*36);   // [64][36] indices
    #pragma unroll
    for (int q = 0; q < KK; q++) {
        mv[srow*36 + sq4*KK + q]  = tv[q];
        mi_[srow*36 + sq4*KK + q] = ti[q];
    }
    __syncthreads();
    if (tid < 64) {
        const int row = tid;
        float* v = &mv[row*36]; int* ix = &mi_[row*36];
        size_t base = ((size_t)(b*NN + n0 + row)*2 + half)*KK;
        for (int p = 0; p < KK; p++) {
            float best = FLT_MAX; int bi = 0x7FFFFFFF; int bs = 0;
            #pragma unroll
            for (int s = 0; s < 36; s++) {
                if (v[s] < best || (v[s] == best && ix[s] < bi)) { best = v[s]; bi = ix[s]; bs = s; }
            }
            g_cv[base + p] = best;
            g_ci[base + p] = bi;
            v[bs] = FLT_MAX;
        }
    }
}

// ------------------------------------------------------------------
// merge2: per row, merge the two halves' top-9 (18 -> 9) into g_nn
// ------------------------------------------------------------------
__global__ void merge2_k() {
    int row = blockIdx.x*256 + threadIdx.x;   // < 16384
    float v[18]; int ix[18];
    #pragma unroll
    for (int s = 0; s < 18; s++) {
        v[s]  = g_cv[(size_t)row*18 + s];
        ix[s] = g_ci[(size_t)row*18 + s];
    }
    int base = row*KK;
    for (int p = 0; p < KK; p++) {
        float best = FLT_MAX; int bi = 0x7FFFFFFF; int bs = 0;
        #pragma unroll
        for (int s = 0; s < 18; s++) {
            if (v[s] < best || (v[s] == best && ix[s] < bi)) { best = v[s]; bi = ix[s]; bs = s; }
        }
        g_nn[base + p] = bi;
        v[bs] = FLT_MAX;
    }
}

// ------------------------------------------------------------------
// P/Q projection GEMM: PQ[b][n][o'] = sum_c x[b][c][n]*M2T[c][o']
// ------------------------------------------------------------------
#define PTM 128
#define PTN 128
#define PCK 16
__global__ __launch_bounds__(256, 2) void pq_k(const float* __restrict__ x) {
    __shared__ float sX[PCK][PTM];
    __shared__ float sW[PCK][PTN];
    const int tid = threadIdx.x;
    const int b  = blockIdx.z;
    const int n0 = blockIdx.x * PTM;
    const int o0 = blockIdx.y * PTN;
    const float* xb = x + (size_t)b*CC*NN;
    const int tx = tid & 15, ty = tid >> 4;

    float acc[8][8];
    #pragma unroll
    for (int i = 0; i < 8; i++)
        #pragma unroll
        for (int j = 0; j < 8; j++) acc[i][j] = 0.f;

    for (int ck = 0; ck < CC; ck += PCK) {
        __syncthreads();
        {
            int e = tid*4; int cc = e>>7; int r = e&127;
            *(float4*)&sX[cc][r] = *(const float4*)&xb[(size_t)(ck+cc)*NN + n0 + r];
            *(float4*)&sW[cc][r] = *(const float4*)&g_M2T[(ck+cc)*512 + o0 + r];
            e += 1024; cc = e>>7; r = e&127;
            *(float4*)&sX[cc][r] = *(const float4*)&xb[(size_t)(ck+cc)*NN + n0 + r];
            *(float4*)&sW[cc][r] = *(const float4*)&g_M2T[(ck+cc)*512 + o0 + r];
        }
        __syncthreads();
        #pragma unroll
        for (int cc = 0; cc < PCK; cc++) {
            float a[8], w[8];
            *(float4*)a     = *(float4*)&sX[cc][ty*8];
            *(float4*)(a+4) = *(float4*)&sX[cc][ty*8+4];
            *(float4*)w     = *(float4*)&sW[cc][tx*8];
            *(float4*)(w+4) = *(float4*)&sW[cc][tx*8+4];
            #pragma unroll
            for (int i = 0; i < 8; i++)
                #pragma unroll
                for (int j = 0; j < 8; j++)
                    acc[i][j] = fmaf(a[i], w[j], acc[i][j]);
        }
    }
    #pragma unroll
    for (int i = 0; i < 8; i++) {
        float* dst = g_PQ + (size_t)(b*NN + n0 + ty*8 + i)*512 + o0 + tx*8;
        *(float4*)dst     = *(float4*)&acc[i][0];
        *(float4*)(dst+4) = *(float4*)&acc[i][4];
    }
}

// ------------------------------------------------------------------
// gather: h = P[n] + Q[j]; per-row max/min over K; partial BN stats.
// ------------------------------------------------------------------
#define GR 32
__global__ __launch_bounds__(256) void gather_k(const float* __restrict__ gamma) {
    __shared__ int sIdx[GR*KK];
    const int tid = threadIdx.x;
    const int row0 = blockIdx.x * GR;
    for (int i = tid; i < GR*KK; i += 256) sIdx[i] = g_nn[row0*KK + i];
    __syncthreads();
    const float gm = gamma[tid];
    float sum = 0.f, ss = 0.f;
    for (int r = 0; r < GR; r++) {
        int grow = row0 + r;
        int b = grow >> 11;
        float p = g_PQ[(size_t)grow*512 + tid];
        float mx = -FLT_MAX, mn = FLT_MAX;
        #pragma unroll
        for (int k = 0; k < KK; k++) {
            int j = sIdx[r*KK + k];
            float q = g_PQ[(size_t)(b*NN + j)*512 + 256 + tid];
            float h = p + q;
            mx = fmaxf(mx, h); mn = fminf(mn, h);
            sum += h; ss = fmaf(h, h, ss);
        }
        g_Hsel[(size_t)grow*CO + tid] = (gm >= 0.f) ? mx : mn;
    }
    g_part[blockIdx.x*512 + tid]       = sum;
    g_part[blockIdx.x*512 + 256 + tid] = ss;
}

// ------------------------------------------------------------------
// finalize BN affine coefficients
// ------------------------------------------------------------------
__global__ void finalize_k(const float* __restrict__ gamma, const float* __restrict__ beta) {
    int o = threadIdx.x;
    float sum = 0.f, ss = 0.f;
    for (int c = 0; c < 512; c++) {
        sum += g_part[c*512 + o];
        ss  += g_part[c*512 + 256 + o];
    }
    float inv_n = 1.f / (float)((size_t)NROWS*KK);
    float mean = sum * inv_n;
    float var  = ss * inv_n - mean*mean;
    float inv  = rsqrtf(var + 1e-5f);
    float a = inv * gamma[o];
    g_scale[o] = a;
    g_shift[o] = beta[o] - mean * a;
}

// ------------------------------------------------------------------
// output: out[b][o][n] = relu(a[o]*Hsel[b][n][o] + c[o]), 32x32 transpose
// ------------------------------------------------------------------
__global__ void out_k(float* __restrict__ out) {
    __shared__ float t[32][33];
    int b = blockIdx.z, n0 = blockIdx.x*32, o0 = blockIdx.y*32;
    int tx = threadIdx.x, ty = threadIdx.y;
    #pragma unroll
    for (int i = 0; i < 4; i++) {
        int n = n0 + ty + i*8;
        t[ty + i*8][tx] = g_Hsel[(size_t)(b*NN + n)*CO + o0 + tx];
    }
    __syncthreads();
    #pragma unroll
    for (int i = 0; i < 4; i++) {
        int o = o0 + ty + i*8;
        float v = fmaf(g_scale[o], t[tx][ty + i*8], g_shift[o]);
        out[(size_t)(b*CO + o)*NN + n0 + tx] = fmaxf(v, 0.f);
    }
}

// ------------------------------------------------------------------
extern "C" void kernel_launch(void* const* d_in, const int* in_sizes, int n_in,
                              void* d_out, int out_size) {
    const float* x     = (const float*)d_in[0];
    const float* W     = (const float*)d_in[1];
    const float* gamma = (const float*)d_in[2];
    const float* beta  = (const float*)d_in[3];
    float* out = (float*)d_out;

    const int GRAM_SMEM = 64*PADA*8 + 64*PADB*4;   // 67584 + 33792 = 101376 B
    cudaFuncSetAttribute(gram_mma_k, cudaFuncAttributeMaxDynamicSharedMemorySize, GRAM_SMEM);

    prep_k<<<256, 256>>>(W);
    sq_k<<<NROWS/256, 256>>>(x);
    xt_k<<<dim3(NN/32, CC/32, BB), dim3(32, 8)>>>(x);
    gram_mma_k<<<dim3(NN/64, 2, BB), 256, GRAM_SMEM>>>();
    merge2_k<<<NROWS/256, 256>>>();
    pq_k<<<dim3(NN/PTM, 512/PTN, BB), 256>>>(x);
    gather_k<<<NROWS/GR, 256>>>(gamma);
    finalize_k<<<1, 256>>>(gamma, beta);
    out_k<<<dim3(NN/32, CO/32, BB), dim3(32, 8)>>>(out);
}

// round 15
// speedup vs baseline: 1.1766x; 1.1766x over previous
#include <cuda_runtime.h>
#include <cstdint>
#include <float.h>

#define BB 8
#define NN 2048
#define CC 128
#define KK 9
#define CO 256
#define NROWS (BB*NN)        // 16384

// ---- scratch (device globals: allocation-free contract) ----
__device__ float g_sq[NROWS];
__device__ int   g_nn[NROWS*KK];
__device__ float g_cv[(size_t)NROWS*2*KK];   // per-half top-9 values
__device__ int   g_ci[(size_t)NROWS*2*KK];   // per-half top-9 indices
__device__ float g_M2T[CC*512];
__device__ float g_PQ[(size_t)NROWS*512];
__device__ float g_Hsel[(size_t)NROWS*CO];
__device__ float g_part[512*512];
__device__ float g_scale[CO];
__device__ float g_shift[CO];
__device__ float g_XT[(size_t)NROWS*CC];     // x transposed [b][n][c], fp32

// warp-level tf32 MMA (sm_80+ generic PTX)
#define MMA_TF32(c0,c1,c2,c3, a0,a1,a2,a3, b0,b1)                          \
    asm volatile("mma.sync.aligned.m16n8k8.row.col.f32.tf32.tf32.f32 "     \
        "{%0,%1,%2,%3}, {%4,%5,%6,%7}, {%8,%9}, {%0,%1,%2,%3};"            \
        : "+f"(c0), "+f"(c1), "+f"(c2), "+f"(c3)                           \
        : "r"(a0), "r"(a1), "r"(a2), "r"(a3), "r"(b0), "r"(b1))

// cheap exact split: hi = truncate-to-tf32 (mask), lo = v - hi (exact fp32).
#define SPLIT(u, hi, lo)                                                   \
    do { hi = (u) & 0xFFFFE000u;                                           \
         lo = __float_as_uint(__uint_as_float(u) - __uint_as_float(hi)); } while (0)

// ------------------------------------------------------------------
// prep: M2T = [[W1-W2];[W2]] transposed to [c][o']
// ------------------------------------------------------------------
__global__ void prep_k(const float* __restrict__ W) {
    int i = blockIdx.x*256 + threadIdx.x;
    if (i >= 512*CC) return;
    int c = i >> 9, o = i & 511;
    float v;
    if (o < CO) v = W[o*256 + c] - W[o*256 + 128 + c];
    else        v = W[(o-CO)*256 + 128 + c];
    g_M2T[c*512 + o] = v;
}

// ------------------------------------------------------------------
// sq: per-point squared norm (x layout [b][c][n])
// ------------------------------------------------------------------
__global__ void sq_k(const float* __restrict__ x) {
    int t = blockIdx.x*256 + threadIdx.x;
    int b = t >> 11, n = t & (NN-1);
    const float* xb = x + (size_t)b*CC*NN + n;
    float s = 0.f;
    #pragma unroll 8
    for (int c = 0; c < CC; c++) { float v = xb[(size_t)c*NN]; s = fmaf(v, v, s); }
    g_sq[t] = s;
}

// ------------------------------------------------------------------
// xt: transpose x [b][c][n] -> XT [b][n][c] (fp32)
// ------------------------------------------------------------------
__global__ void xt_k(const float* __restrict__ x) {
    __shared__ float t[32][33];
    int b = blockIdx.z, n0 = blockIdx.x*32, c0 = blockIdx.y*32;
    int tx = threadIdx.x, ty = threadIdx.y;   // 32 x 8
    #pragma unroll
    for (int i = 0; i < 4; i++)
        t[ty + i*8][tx] = x[((size_t)(b*CC + c0 + ty + i*8))*NN + n0 + tx];
    __syncthreads();
    #pragma unroll
    for (int i = 0; i < 4; i++) {
        int n = n0 + ty + i*8;
        g_XT[((size_t)(b*NN + n))*CC + c0 + tx] = t[tx][ty + i*8];
    }
}

// ------------------------------------------------------------------
// gram_mma v11: R12 structure, pass-outermost MMA ordering.
// CTA = 128-row strip x 1024 columns (half). Grid (16, 2, 8) = 256 CTAs
// -> 2 CTAs/SM (99KB smem), 16 warps/SM.
// 256 threads = 8 warps (4m x 2n), warp tile 32x32 over 128x64 tiles.
// Per k-step: 16 LDS + 32 split-ALU + 24 MMA in 3 rounds of 8 independent.
// ------------------------------------------------------------------
#define PAD 132
#define SDP 65

__global__ __launch_bounds__(256, 2) void gram_mma_k() {
    extern __shared__ float sm[];
    float* sA = sm;                     // 128*132 fp32
    float* sB = sm + 128*PAD;           // 64*132 fp32
    float* sD = sB;                     // overlay: 128*65 <= 64*132
    __shared__ float sSq[64];

    const int tid  = threadIdx.x;
    const int warp = tid >> 5, lane = tid & 31;
    const int qr = lane >> 2, qc = lane & 3;
    const int wm = (warp & 3) * 32;    // row base within 128-strip
    const int wn = (warp >> 2) * 32;   // col base within 64-tile
    const int half = blockIdx.y;
    const int b = blockIdx.z, n0 = blockIdx.x*128;

    // topk scan mapping: 2 threads per row
    const int srow = tid & 127;
    const int shalf = tid >> 7;

    // load A strip (rows n0..n0+127): 128x128 fp32
    {
        const float4* src = (const float4*)(g_XT + (size_t)(b*NN + n0)*CC);
        #pragma unroll
        for (int it = 0; it < 16; it++) {
            int g = it*256 + tid;
            int row = g >> 5, c4 = (g & 31) * 4;
            *(float4*)&sA[row*PAD + c4] = src[g];
        }
    }

    float tv[9]; int ti[9];            // ONE top-9 list per thread
    #pragma unroll
    for (int q = 0; q < KK; q++) { tv[q] = FLT_MAX; ti[q] = 0x7FFFFFFF; }

    for (int mt = 0; mt < 16; mt++) {
        const int m0 = (half*16 + mt)*64;
        __syncthreads();   // prev scan done; B/sD region reusable
        {
            const float4* src = (const float4*)(g_XT + (size_t)(b*NN + m0)*CC);
            #pragma unroll
            for (int it = 0; it < 8; it++) {
                int g = it*256 + tid;
                int row = g >> 5, c4 = (g & 31) * 4;
                *(float4*)&sB[row*PAD + c4] = src[g];
            }
            if (tid < 64) sSq[tid] = g_sq[b*NN + m0 + tid];
        }
        __syncthreads();

        float acc[2][4][4];
        #pragma unroll
        for (int mi = 0; mi < 2; mi++)
            #pragma unroll
            for (int nj = 0; nj < 4; nj++)
                #pragma unroll
                for (int r = 0; r < 4; r++) acc[mi][nj][r] = 0.f;

        // per k-step: 16 LDS, bitmask split, 24 MMAs in 3 independent rounds
        #pragma unroll
        for (int ks = 0; ks < 16; ks++) {
            const int k0 = ks*8;
            uint32_t ah[2][4], al[2][4], bh[4][2], bl[4][2];
            #pragma unroll
            for (int mi = 0; mi < 2; mi++) {
                const uint32_t* p = (const uint32_t*)(sA + (wm + 16*mi + qr)*PAD + k0 + qc);
                uint32_t u0 = p[0], u1 = p[8*PAD], u2 = p[4], u3 = p[8*PAD + 4];
                SPLIT(u0, ah[mi][0], al[mi][0]);
                SPLIT(u1, ah[mi][1], al[mi][1]);
                SPLIT(u2, ah[mi][2], al[mi][2]);
                SPLIT(u3, ah[mi][3], al[mi][3]);
            }
            #pragma unroll
            for (int nj = 0; nj < 4; nj++) {
                const uint32_t* p = (const uint32_t*)(sB + (wn + 8*nj + qr)*PAD + k0 + qc);
                uint32_t u0 = p[0], u1 = p[4];
                SPLIT(u0, bh[nj][0], bl[nj][0]);
                SPLIT(u1, bh[nj][1], bl[nj][1]);
            }
            // round 1: Ah*Bh (8 independent MMAs)
            #pragma unroll
            for (int mi = 0; mi < 2; mi++)
                #pragma unroll
                for (int nj = 0; nj < 4; nj++)
                    MMA_TF32(acc[mi][nj][0], acc[mi][nj][1], acc[mi][nj][2], acc[mi][nj][3],
                             ah[mi][0], ah[mi][1], ah[mi][2], ah[mi][3], bh[nj][0], bh[nj][1]);
            // round 2: Al*Bh
            #pragma unroll
            for (int mi = 0; mi < 2; mi++)
                #pragma unroll
                for (int nj = 0; nj < 4; nj++)
                    MMA_TF32(acc[mi][nj][0], acc[mi][nj][1], acc[mi][nj][2], acc[mi][nj][3],
                             al[mi][0], al[mi][1], al[mi][2], al[mi][3], bh[nj][0], bh[nj][1]);
            // round 3: Ah*Bl
            #pragma unroll
            for (int mi = 0; mi < 2; mi++)
                #pragma unroll
                for (int nj = 0; nj < 4; nj++)
                    MMA_TF32(acc[mi][nj][0], acc[mi][nj][1], acc[mi][nj][2], acc[mi][nj][3],
                             ah[mi][0], ah[mi][1], ah[mi][2], ah[mi][3], bl[nj][0], bl[nj][1]);
        }

        // stage d-tile (all warps done reading B -> overlay safe)
        __syncthreads();
        #pragma unroll
        for (int mi = 0; mi < 2; mi++)
            #pragma unroll
            for (int nj = 0; nj < 4; nj++)
                #pragma unroll
                for (int r = 0; r < 4; r++) {
                    const int row = wm + 16*mi + 8*(r >> 1) + qr;
                    const int col = wn + 8*nj + 2*qc + (r & 1);
                    sD[row*SDP + col] = sSq[col] - 2.f*acc[mi][nj][r];
                }
        __syncthreads();

        // top-9 scan: thread (srow, shalf) scans 32 cols, ascending m
        {
            const float* dr = sD + srow*SDP + shalf*32;
            const int mb = m0 + shalf*32;
            #pragma unroll 8
            for (int j = 0; j < 32; j++) {
                float d = dr[j];
                if (d < tv[8]) {
                    tv[8] = d; ti[8] = mb + j;
                    #pragma unroll
                    for (int q = 8; q > 0; q--) {
                        if (tv[q] < tv[q-1]) {
                            float fv = tv[q]; tv[q] = tv[q-1]; tv[q-1] = fv;
                            int iv = ti[q];  ti[q] = ti[q-1]; ti[q-1] = iv;
                        }
                    }
                }
            }
        }
    }

    // in-CTA merge: 2 threads per row x 9 = 18 -> 9 for this half
    __syncthreads();
    float* mv  = sm;                   // [128][18] values
    int*   mi_ = (int*)(sm + 128*18);  // [128][18] indices
    #pragma unroll
    for (int q = 0; q < KK; q++) {
        mv[srow*18 + shalf*KK + q]  = tv[q];
        mi_[srow*18 + shalf*KK + q] = ti[q];
    }
    __syncthreads();
    if (tid < 128) {
        const int row = tid;
        float* v = &mv[row*18]; int* ix = &mi_[row*18];
        size_t base = ((size_t)(b*NN + n0 + row)*2 + half)*KK;
        for (int p = 0; p < KK; p++) {
            float best = FLT_MAX; int bi = 0x7FFFFFFF; int bs = 0;
            #pragma unroll
            for (int s = 0; s < 18; s++) {
                if (v[s] < best || (v[s] == best && ix[s] < bi)) { best = v[s]; bi = ix[s]; bs = s; }
            }
            g_cv[base + p] = best;
            g_ci[base + p] = bi;
            v[bs] = FLT_MAX;
        }
    }
}

// ------------------------------------------------------------------
// merge2: per row, merge the two halves' top-9 (18 -> 9) into g_nn
// ------------------------------------------------------------------
__global__ void merge2_k() {
    int row = blockIdx.x*256 + threadIdx.x;   // < 16384
    float v[18]; int ix[18];
    #pragma unroll
    for (int s = 0; s < 18; s++) {
        v[s]  = g_cv[(size_t)row*18 + s];
        ix[s] = g_ci[(size_t)row*18 + s];
    }
    int base = row*KK;
    for (int p = 0; p < KK; p++) {
        float best = FLT_MAX; int bi = 0x7FFFFFFF; int bs = 0;
        #pragma unroll
        for (int s = 0; s < 18; s++) {
            if (v[s] < best || (v[s] == best && ix[s] < bi)) { best = v[s]; bi = ix[s]; bs = s; }
        }
        g_nn[base + p] = bi;
        v[bs] = FLT_MAX;
    }
}

// ------------------------------------------------------------------
// P/Q projection GEMM: PQ[b][n][o'] = sum_c x[b][c][n]*M2T[c][o']
// ------------------------------------------------------------------
#define PTM 128
#define PTN 128
#define PCK 16
__global__ __launch_bounds__(256, 2) void pq_k(const float* __restrict__ x) {
    __shared__ float sX[PCK][PTM];
    __shared__ float sW[PCK][PTN];
    const int tid = threadIdx.x;
    const int b  = blockIdx.z;
    const int n0 = blockIdx.x * PTM;
    const int o0 = blockIdx.y * PTN;
    const float* xb = x + (size_t)b*CC*NN;
    const int tx = tid & 15, ty = tid >> 4;

    float acc[8][8];
    #pragma unroll
    for (int i = 0; i < 8; i++)
        #pragma unroll
        for (int j = 0; j < 8; j++) acc[i][j] = 0.f;

    for (int ck = 0; ck < CC; ck += PCK) {
        __syncthreads();
        {
            int e = tid*4; int cc = e>>7; int r = e&127;
            *(float4*)&sX[cc][r] = *(const float4*)&xb[(size_t)(ck+cc)*NN + n0 + r];
            *(float4*)&sW[cc][r] = *(const float4*)&g_M2T[(ck+cc)*512 + o0 + r];
            e += 1024; cc = e>>7; r = e&127;
            *(float4*)&sX[cc][r] = *(const float4*)&xb[(size_t)(ck+cc)*NN + n0 + r];
            *(float4*)&sW[cc][r] = *(const float4*)&g_M2T[(ck+cc)*512 + o0 + r];
        }
        __syncthreads();
        #pragma unroll
        for (int cc = 0; cc < PCK; cc++) {
            float a[8], w[8];
            *(float4*)a     = *(float4*)&sX[cc][ty*8];
            *(float4*)(a+4) = *(float4*)&sX[cc][ty*8+4];
            *(float4*)w     = *(float4*)&sW[cc][tx*8];
            *(float4*)(w+4) = *(float4*)&sW[cc][tx*8+4];
            #pragma unroll
            for (int i = 0; i < 8; i++)
                #pragma unroll
                for (int j = 0; j < 8; j++)
                    acc[i][j] = fmaf(a[i], w[j], acc[i][j]);
        }
    }
    #pragma unroll
    for (int i = 0; i < 8; i++) {
        float* dst = g_PQ + (size_t)(b*NN + n0 + ty*8 + i)*512 + o0 + tx*8;
        *(float4*)dst     = *(float4*)&acc[i][0];
        *(float4*)(dst+4) = *(float4*)&acc[i][4];
    }
}

// ------------------------------------------------------------------
// gather: h = P[n] + Q[j]; per-row max/min over K; partial BN stats.
// ------------------------------------------------------------------
#define GR 32
__global__ __launch_bounds__(256) void gather_k(const float* __restrict__ gamma) {
    __shared__ int sIdx[GR*KK];
    const int tid = threadIdx.x;
    const int row0 = blockIdx.x * GR;
    for (int i = tid; i < GR*KK; i += 256) sIdx[i] = g_nn[row0*KK + i];
    __syncthreads();
    const float gm = gamma[tid];
    float sum = 0.f, ss = 0.f;
    for (int r = 0; r < GR; r++) {
        int grow = row0 + r;
        int b = grow >> 11;
        float p = g_PQ[(size_t)grow*512 + tid];
        float mx = -FLT_MAX, mn = FLT_MAX;
        #pragma unroll
        for (int k = 0; k < KK; k++) {
            int j = sIdx[r*KK + k];
            float q = g_PQ[(size_t)(b*NN + j)*512 + 256 + tid];
            float h = p + q;
            mx = fmaxf(mx, h); mn = fminf(mn, h);
            sum += h; ss = fmaf(h, h, ss);
        }
        g_Hsel[(size_t)grow*CO + tid] = (gm >= 0.f) ? mx : mn;
    }
    g_part[blockIdx.x*512 + tid]       = sum;
    g_part[blockIdx.x*512 + 256 + tid] = ss;
}

// ------------------------------------------------------------------
// finalize BN affine coefficients
// ------------------------------------------------------------------
__global__ void finalize_k(const float* __restrict__ gamma, const float* __restrict__ beta) {
    int o = threadIdx.x;
    float sum = 0.f, ss = 0.f;
    for (int c = 0; c < 512; c++) {
        sum += g_part[c*512 + o];
        ss  += g_part[c*512 + 256 + o];
    }
    float inv_n = 1.f / (float)((size_t)NROWS*KK);
    float mean = sum * inv_n;
    float var  = ss * inv_n - mean*mean;
    float inv  = rsqrtf(var + 1e-5f);
    float a = inv * gamma[o];
    g_scale[o] = a;
    g_shift[o] = beta[o] - mean * a;
}

// ------------------------------------------------------------------
// output: out[b][o][n] = relu(a[o]*Hsel[b][n][o] + c[o]), 32x32 transpose
// ------------------------------------------------------------------
__global__ void out_k(float* __restrict__ out) {
    __shared__ float t[32][33];
    int b = blockIdx.z, n0 = blockIdx.x*32, o0 = blockIdx.y*32;
    int tx = threadIdx.x, ty = threadIdx.y;
    #pragma unroll
    for (int i = 0; i < 4; i++) {
        int n = n0 + ty + i*8;
        t[ty + i*8][tx] = g_Hsel[(size_t)(b*NN + n)*CO + o0 + tx];
    }
    __syncthreads();
    #pragma unroll
    for (int i = 0; i < 4; i++) {
        int o = o0 + ty + i*8;
        float v = fmaf(g_scale[o], t[tx][ty + i*8], g_shift[o]);
        out[(size_t)(b*CO + o)*NN + n0 + tx] = fmaxf(v, 0.f);
    }
}

// ------------------------------------------------------------------
extern "C" void kernel_launch(void* const* d_in, const int* in_sizes, int n_in,
                              void* d_out, int out_size) {
    const float* x     = (const float*)d_in[0];
    const float* W     = (const float*)d_in[1];
    const float* gamma = (const float*)d_in[2];
    const float* beta  = (const float*)d_in[3];
    float* out = (float*)d_out;

    const int GRAM_SMEM = 192 * PAD * 4;   // 101376 B -> 2 CTAs/SM
    cudaFuncSetAttribute(gram_mma_k, cudaFuncAttributeMaxDynamicSharedMemorySize, GRAM_SMEM);

    prep_k<<<256, 256>>>(W);
    sq_k<<<NROWS/256, 256>>>(x);
    xt_k<<<dim3(NN/32, CC/32, BB), dim3(32, 8)>>>(x);
    gram_mma_k<<<dim3(NN/128, 2, BB), 256, GRAM_SMEM>>>();
    merge2_k<<<NROWS/256, 256>>>();
    pq_k<<<dim3(NN/PTM, 512/PTN, BB), 256>>>(x);
    gather_k<<<NROWS/GR, 256>>>(gamma);
    finalize_k<<<1, 256>>>(gamma, beta);
    out_k<<<dim3(NN/32, CO/32, BB), dim3(32, 8)>>>(out);
}

// round 17
// speedup vs baseline: 1.2728x; 1.0817x over previous
#include <cuda_runtime.h>
#include <cstdint>
#include <float.h>

#define BB 8
#define NN 2048
#define CC 128
#define KK 9
#define CO 256
#define NROWS (BB*NN)        // 16384

// ---- scratch (device globals: allocation-free contract) ----
__device__ float g_sq[NROWS];
__device__ int   g_nn[NROWS*KK];
__device__ float g_cv[(size_t)NROWS*2*KK];   // per-half top-9 values
__device__ int   g_ci[(size_t)NROWS*2*KK];   // per-half top-9 indices
__device__ float g_M2T[CC*512];
__device__ float g_M2TT[512*CC];             // [o'][c] (K-contiguous for mma B)
__device__ float g_PQ[(size_t)NROWS*512];
__device__ float g_Hsel[(size_t)NROWS*CO];
__device__ float g_part[512*512];
__device__ float g_scale[CO];
__device__ float g_shift[CO];
__device__ float g_XT[(size_t)NROWS*CC];     // x transposed [b][n][c], fp32

// warp-level tf32 MMA (sm_80+ generic PTX)
#define MMA_TF32(c0,c1,c2,c3, a0,a1,a2,a3, b0,b1)                          \
    asm volatile("mma.sync.aligned.m16n8k8.row.col.f32.tf32.tf32.f32 "     \
        "{%0,%1,%2,%3}, {%4,%5,%6,%7}, {%8,%9}, {%0,%1,%2,%3};"            \
        : "+f"(c0), "+f"(c1), "+f"(c2), "+f"(c3)                           \
        : "r"(a0), "r"(a1), "r"(a2), "r"(a3), "r"(b0), "r"(b1))

// cheap exact split: hi = truncate-to-tf32 (mask), lo = v - hi (exact fp32).
#define SPLIT(u, hi, lo)                                                   \
    do { hi = (u) & 0xFFFFE000u;                                           \
         lo = __float_as_uint(__uint_as_float(u) - __uint_as_float(hi)); } while (0)

// ------------------------------------------------------------------
// prep: M2T = [[W1-W2];[W2]] transposed to [c][o'], plus M2TT = [o'][c]
// ------------------------------------------------------------------
__global__ void prep_k(const float* __restrict__ W) {
    int i = blockIdx.x*256 + threadIdx.x;
    if (i >= 512*CC) return;
    int c = i >> 9, o = i & 511;
    float v;
    if (o < CO) v = W[o*256 + c] - W[o*256 + 128 + c];
    else        v = W[(o-CO)*256 + 128 + c];
    g_M2T[c*512 + o] = v;
    g_M2TT[o*CC + c] = v;
}

// ------------------------------------------------------------------
// sq: per-point squared norm (x layout [b][c][n])
// ------------------------------------------------------------------
__global__ void sq_k(const float* __restrict__ x) {
    int t = blockIdx.x*256 + threadIdx.x;
    int b = t >> 11, n = t & (NN-1);
    const float* xb = x + (size_t)b*CC*NN + n;
    float s = 0.f;
    #pragma unroll 8
    for (int c = 0; c < CC; c++) { float v = xb[(size_t)c*NN]; s = fmaf(v, v, s); }
    g_sq[t] = s;
}

// ------------------------------------------------------------------
// xt: transpose x [b][c][n] -> XT [b][n][c] (fp32)
// ------------------------------------------------------------------
__global__ void xt_k(const float* __restrict__ x) {
    __shared__ float t[32][33];
    int b = blockIdx.z, n0 = blockIdx.x*32, c0 = blockIdx.y*32;
    int tx = threadIdx.x, ty = threadIdx.y;   // 32 x 8
    #pragma unroll
    for (int i = 0; i < 4; i++)
        t[ty + i*8][tx] = x[((size_t)(b*CC + c0 + ty + i*8))*NN + n0 + tx];
    __syncthreads();
    #pragma unroll
    for (int i = 0; i < 4; i++) {
        int n = n0 + ty + i*8;
        g_XT[((size_t)(b*NN + n))*CC + c0 + tx] = t[tx][ty + i*8];
    }
}

// ------------------------------------------------------------------
// gram_mma v11 (unchanged, best known): tf32 3-pass Gram + staged top-9.
// ------------------------------------------------------------------
#define PAD 132
#define SDP 65

__global__ __launch_bounds__(256, 2) void gram_mma_k() {
    extern __shared__ float sm[];
    float* sA = sm;                     // 128*132 fp32
    float* sB = sm + 128*PAD;           // 64*132 fp32
    float* sD = sB;                     // overlay: 128*65 <= 64*132
    __shared__ float sSq[64];

    const int tid  = threadIdx.x;
    const int warp = tid >> 5, lane = tid & 31;
    const int qr = lane >> 2, qc = lane & 3;
    const int wm = (warp & 3) * 32;
    const int wn = (warp >> 2) * 32;
    const int half = blockIdx.y;
    const int b = blockIdx.z, n0 = blockIdx.x*128;

    const int srow = tid & 127;
    const int shalf = tid >> 7;

    {
        const float4* src = (const float4*)(g_XT + (size_t)(b*NN + n0)*CC);
        #pragma unroll
        for (int it = 0; it < 16; it++) {
            int g = it*256 + tid;
            int row = g >> 5, c4 = (g & 31) * 4;
            *(float4*)&sA[row*PAD + c4] = src[g];
        }
    }

    float tv[9]; int ti[9];
    #pragma unroll
    for (int q = 0; q < KK; q++) { tv[q] = FLT_MAX; ti[q] = 0x7FFFFFFF; }

    for (int mt = 0; mt < 16; mt++) {
        const int m0 = (half*16 + mt)*64;
        __syncthreads();
        {
            const float4* src = (const float4*)(g_XT + (size_t)(b*NN + m0)*CC);
            #pragma unroll
            for (int it = 0; it < 8; it++) {
                int g = it*256 + tid;
                int row = g >> 5, c4 = (g & 31) * 4;
                *(float4*)&sB[row*PAD + c4] = src[g];
            }
            if (tid < 64) sSq[tid] = g_sq[b*NN + m0 + tid];
        }
        __syncthreads();

        float acc[2][4][4];
        #pragma unroll
        for (int mi = 0; mi < 2; mi++)
            #pragma unroll
            for (int nj = 0; nj < 4; nj++)
                #pragma unroll
                for (int r = 0; r < 4; r++) acc[mi][nj][r] = 0.f;

        #pragma unroll
        for (int ks = 0; ks < 16; ks++) {
            const int k0 = ks*8;
            uint32_t ah[2][4], al[2][4], bh[4][2], bl[4][2];
            #pragma unroll
            for (int mi = 0; mi < 2; mi++) {
                const uint32_t* p = (const uint32_t*)(sA + (wm + 16*mi + qr)*PAD + k0 + qc);
                uint32_t u0 = p[0], u1 = p[8*PAD], u2 = p[4], u3 = p[8*PAD + 4];
                SPLIT(u0, ah[mi][0], al[mi][0]);
                SPLIT(u1, ah[mi][1], al[mi][1]);
                SPLIT(u2, ah[mi][2], al[mi][2]);
                SPLIT(u3, ah[mi][3], al[mi][3]);
            }
            #pragma unroll
            for (int nj = 0; nj < 4; nj++) {
                const uint32_t* p = (const uint32_t*)(sB + (wn + 8*nj + qr)*PAD + k0 + qc);
                uint32_t u0 = p[0], u1 = p[4];
                SPLIT(u0, bh[nj][0], bl[nj][0]);
                SPLIT(u1, bh[nj][1], bl[nj][1]);
            }
            #pragma unroll
            for (int mi = 0; mi < 2; mi++)
                #pragma unroll
                for (int nj = 0; nj < 4; nj++)
                    MMA_TF32(acc[mi][nj][0], acc[mi][nj][1], acc[mi][nj][2], acc[mi][nj][3],
                             ah[mi][0], ah[mi][1], ah[mi][2], ah[mi][3], bh[nj][0], bh[nj][1]);
            #pragma unroll
            for (int mi = 0; mi < 2; mi++)
                #pragma unroll
                for (int nj = 0; nj < 4; nj++)
                    MMA_TF32(acc[mi][nj][0], acc[mi][nj][1], acc[mi][nj][2], acc[mi][nj][3],
                             al[mi][0], al[mi][1], al[mi][2], al[mi][3], bh[nj][0], bh[nj][1]);
            #pragma unroll
            for (int mi = 0; mi < 2; mi++)
                #pragma unroll
                for (int nj = 0; nj < 4; nj++)
                    MMA_TF32(acc[mi][nj][0], acc[mi][nj][1], acc[mi][nj][2], acc[mi][nj][3],
                             ah[mi][0], ah[mi][1], ah[mi][2], ah[mi][3], bl[nj][0], bl[nj][1]);
        }

        __syncthreads();
        #pragma unroll
        for (int mi = 0; mi < 2; mi++)
            #pragma unroll
            for (int nj = 0; nj < 4; nj++)
                #pragma unroll
                for (int r = 0; r < 4; r++) {
                    const int row = wm + 16*mi + 8*(r >> 1) + qr;
                    const int col = wn + 8*nj + 2*qc + (r & 1);
                    sD[row*SDP + col] = sSq[col] - 2.f*acc[mi][nj][r];
                }
        __syncthreads();

        {
            const float* dr = sD + srow*SDP + shalf*32;
            const int mb = m0 + shalf*32;
            #pragma unroll 8
            for (int j = 0; j < 32; j++) {
                float d = dr[j];
                if (d < tv[8]) {
                    tv[8] = d; ti[8] = mb + j;
                    #pragma unroll
                    for (int q = 8; q > 0; q--) {
                        if (tv[q] < tv[q-1]) {
                            float fv = tv[q]; tv[q] = tv[q-1]; tv[q-1] = fv;
                            int iv = ti[q];  ti[q] = ti[q-1]; ti[q-1] = iv;
                        }
                    }
                }
            }
        }
    }

    __syncthreads();
    float* mv  = sm;
    int*   mi_ = (int*)(sm + 128*18);
    #pragma unroll
    for (int q = 0; q < KK; q++) {
        mv[srow*18 + shalf*KK + q]  = tv[q];
        mi_[srow*18 + shalf*KK + q] = ti[q];
    }
    __syncthreads();
    if (tid < 128) {
        const int row = tid;
        float* v = &mv[row*18]; int* ix = &mi_[row*18];
        size_t base = ((size_t)(b*NN + n0 + row)*2 + half)*KK;
        for (int p = 0; p < KK; p++) {
            float best = FLT_MAX; int bi = 0x7FFFFFFF; int bs = 0;
            #pragma unroll
            for (int s = 0; s < 18; s++) {
                if (v[s] < best || (v[s] == best && ix[s] < bi)) { best = v[s]; bi = ix[s]; bs = s; }
            }
            g_cv[base + p] = best;
            g_ci[base + p] = bi;
            v[bs] = FLT_MAX;
        }
    }
}

// ------------------------------------------------------------------
// merge2: per row, merge the two halves' top-9 (18 -> 9) into g_nn
// ------------------------------------------------------------------
__global__ void merge2_k() {
    int row = blockIdx.x*256 + threadIdx.x;
    float v[18]; int ix[18];
    #pragma unroll
    for (int s = 0; s < 18; s++) {
        v[s]  = g_cv[(size_t)row*18 + s];
        ix[s] = g_ci[(size_t)row*18 + s];
    }
    int base = row*KK;
    for (int p = 0; p < KK; p++) {
        float best = FLT_MAX; int bi = 0x7FFFFFFF; int bs = 0;
        #pragma unroll
        for (int s = 0; s < 18; s++) {
            if (v[s] < best || (v[s] == best && ix[s] < bi)) { best = v[s]; bi = ix[s]; bs = s; }
        }
        g_nn[base + p] = bi;
        v[bs] = FLT_MAX;
    }
}

// ------------------------------------------------------------------
// pq_mma: tf32 3-pass GEMM. PQ[row][o'] = sum_c XT[row][c] * M2TT[o'][c].
// CTA = 128-row strip x 64 o'-cols; grid (16, 8, 8) = 1024 CTAs, 2/SM.
// Same inner loop as gram; epilogue = coalesced float2 stores.
// ------------------------------------------------------------------
__global__ __launch_bounds__(256, 2) void pq_mma_k() {
    extern __shared__ float sm[];
    float* sA = sm;                     // 128*132 fp32
    float* sW = sm + 128*PAD;           // 64*132 fp32

    const int tid  = threadIdx.x;
    const int warp = tid >> 5, lane = tid & 31;
    const int qr = lane >> 2, qc = lane & 3;
    const int wm = (warp & 3) * 32;
    const int wn = (warp >> 2) * 32;
    const int b = blockIdx.z, n0 = blockIdx.x*128, o0 = blockIdx.y*64;

    {
        const float4* src = (const float4*)(g_XT + (size_t)(b*NN + n0)*CC);
        const float4* srcW = (const float4*)(g_M2TT + (size_t)o0*CC);
        #pragma unroll
        for (int it = 0; it < 16; it++) {
            int g = it*256 + tid;
            int row = g >> 5, c4 = (g & 31) * 4;
            *(float4*)&sA[row*PAD + c4] = src[g];
        }
        #pragma unroll
        for (int it = 0; it < 8; it++) {
            int g = it*256 + tid;
            int row = g >> 5, c4 = (g & 31) * 4;
            *(float4*)&sW[row*PAD + c4] = srcW[g];
        }
    }
    __syncthreads();

    float acc[2][4][4];
    #pragma unroll
    for (int mi = 0; mi < 2; mi++)
        #pragma unroll
        for (int nj = 0; nj < 4; nj++)
            #pragma unroll
            for (int r = 0; r < 4; r++) acc[mi][nj][r] = 0.f;

    #pragma unroll
    for (int ks = 0; ks < 16; ks++) {
        const int k0 = ks*8;
        uint32_t ah[2][4], al[2][4], bh[4][2], bl[4][2];
        #pragma unroll
        for (int mi = 0; mi < 2; mi++) {
            const uint32_t* p = (const uint32_t*)(sA + (wm + 16*mi + qr)*PAD + k0 + qc);
            uint32_t u0 = p[0], u1 = p[8*PAD], u2 = p[4], u3 = p[8*PAD + 4];
            SPLIT(u0, ah[mi][0], al[mi][0]);
            SPLIT(u1, ah[mi][1], al[mi][1]);
            SPLIT(u2, ah[mi][2], al[mi][2]);
            SPLIT(u3, ah[mi][3], al[mi][3]);
        }
        #pragma unroll
        for (int nj = 0; nj < 4; nj++) {
            const uint32_t* p = (const uint32_t*)(sW + (wn + 8*nj + qr)*PAD + k0 + qc);
            uint32_t u0 = p[0], u1 = p[4];
            SPLIT(u0, bh[nj][0], bl[nj][0]);
            SPLIT(u1, bh[nj][1], bl[nj][1]);
        }
        #pragma unroll
        for (int mi = 0; mi < 2; mi++)
            #pragma unroll
            for (int nj = 0; nj < 4; nj++)
                MMA_TF32(acc[mi][nj][0], acc[mi][nj][1], acc[mi][nj][2], acc[mi][nj][3],
                         ah[mi][0], ah[mi][1], ah[mi][2], ah[mi][3], bh[nj][0], bh[nj][1]);
        #pragma unroll
        for (int mi = 0; mi < 2; mi++)
            #pragma unroll
            for (int nj = 0; nj < 4; nj++)
                MMA_TF32(acc[mi][nj][0], acc[mi][nj][1], acc[mi][nj][2], acc[mi][nj][3],
                         al[mi][0], al[mi][1], al[mi][2], al[mi][3], bh[nj][0], bh[nj][1]);
        #pragma unroll
        for (int mi = 0; mi < 2; mi++)
            #pragma unroll
            for (int nj = 0; nj < 4; nj++)
                MMA_TF32(acc[mi][nj][0], acc[mi][nj][1], acc[mi][nj][2], acc[mi][nj][3],
                         ah[mi][0], ah[mi][1], ah[mi][2], ah[mi][3], bl[nj][0], bl[nj][1]);
    }

    // epilogue: float2 stores (cols 2qc, 2qc+1 adjacent)
    #pragma unroll
    for (int mi = 0; mi < 2; mi++)
        #pragma unroll
        for (int nj = 0; nj < 4; nj++) {
            const int col = o0 + wn + 8*nj + 2*qc;
            {
                const int row = wm + 16*mi + qr;
                float* dst = g_PQ + (size_t)(b*NN + n0 + row)*512 + col;
                *(float2*)dst = make_float2(acc[mi][nj][0], acc[mi][nj][1]);
            }
            {
                const int row = wm + 16*mi + 8 + qr;
                float* dst = g_PQ + (size_t)(b*NN + n0 + row)*512 + col;
                *(float2*)dst = make_float2(acc[mi][nj][2], acc[mi][nj][3]);
            }
        }
}

// ------------------------------------------------------------------
// gather: h = P[n] + Q[j]; per-row max/min over K; partial BN stats.
// ------------------------------------------------------------------
#define GR 32
__global__ __launch_bounds__(256) void gather_k(const float* __restrict__ gamma) {
    __shared__ int sIdx[GR*KK];
    const int tid = threadIdx.x;
    const int row0 = blockIdx.x * GR;
    for (int i = tid; i < GR*KK; i += 256) sIdx[i] = g_nn[row0*KK + i];
    __syncthreads();
    const float gm = gamma[tid];
    float sum = 0.f, ss = 0.f;
    for (int r = 0; r < GR; r++) {
        int grow = row0 + r;
        int b = grow >> 11;
        float p = g_PQ[(size_t)grow*512 + tid];
        float mx = -FLT_MAX, mn = FLT_MAX;
        #pragma unroll
        for (int k = 0; k < KK; k++) {
            int j = sIdx[r*KK + k];
            float q = g_PQ[(size_t)(b*NN + j)*512 + 256 + tid];
            float h = p + q;
            mx = fmaxf(mx, h); mn = fminf(mn, h);
            sum += h; ss = fmaf(h, h, ss);
        }
        g_Hsel[(size_t)grow*CO + tid] = (gm >= 0.f) ? mx : mn;
    }
    g_part[blockIdx.x*512 + tid]       = sum;
    g_part[blockIdx.x*512 + 256 + tid] = ss;
}

// ------------------------------------------------------------------
// finalize BN affine coefficients
// ------------------------------------------------------------------
__global__ void finalize_k(const float* __restrict__ gamma, const float* __restrict__ beta) {
    int o = threadIdx.x;
    float sum = 0.f, ss = 0.f;
    for (int c = 0; c < 512; c++) {
        sum += g_part[c*512 + o];
        ss  += g_part[c*512 + 256 + o];
    }
    float inv_n = 1.f / (float)((size_t)NROWS*KK);
    float mean = sum * inv_n;
    float var  = ss * inv_n - mean*mean;
    float inv  = rsqrtf(var + 1e-5f);
    float a = inv * gamma[o];
    g_scale[o] = a;
    g_shift[o] = beta[o] - mean * a;
}

// ------------------------------------------------------------------
// output: out[b][o][n] = relu(a[o]*Hsel[b][n][o] + c[o]), 32x32 transpose
// ------------------------------------------------------------------
__global__ void out_k(float* __restrict__ out) {
    __shared__ float t[32][33];
    int b = blockIdx.z, n0 = blockIdx.x*32, o0 = blockIdx.y*32;
    int tx = threadIdx.x, ty = threadIdx.y;
    #pragma unroll
    for (int i = 0; i < 4; i++) {
        int n = n0 + ty + i*8;
        t[ty + i*8][tx] = g_Hsel[(size_t)(b*NN + n)*CO + o0 + tx];
    }
    __syncthreads();
    #pragma unroll
    for (int i = 0; i < 4; i++) {
        int o = o0 + ty + i*8;
        float v = fmaf(g_scale[o], t[tx][ty + i*8], g_shift[o]);
        out[(size_t)(b*CO + o)*NN + n0 + tx] = fmaxf(v, 0.f);
    }
}

// ------------------------------------------------------------------
extern "C" void kernel_launch(void* const* d_in, const int* in_sizes, int n_in,
                              void* d_out, int out_size) {
    const float* x     = (const float*)d_in[0];
    const float* W     = (const float*)d_in[1];
    const float* gamma = (const float*)d_in[2];
    const float* beta  = (const float*)d_in[3];
    float* out = (float*)d_out;

    const int GRAM_SMEM = 192 * PAD * 4;   // 101376 B -> 2 CTAs/SM
    cudaFuncSetAttribute(gram_mma_k, cudaFuncAttributeMaxDynamicSharedMemorySize, GRAM_SMEM);
    cudaFuncSetAttribute(pq_mma_k,  cudaFuncAttributeMaxDynamicSharedMemorySize, GRAM_SMEM);

    prep_k<<<256, 256>>>(W);
    sq_k<<<NROWS/256, 256>>>(x);
    xt_k<<<dim3(NN/32, CC/32, BB), dim3(32, 8)>>>(x);
    gram_mma_k<<<dim3(NN/128, 2, BB), 256, GRAM_SMEM>>>();
    merge2_k<<<NROWS/256, 256>>>();
    pq_mma_k<<<dim3(NN/128, 8, BB), 256, GRAM_SMEM>>>();
    gather_k<<<NROWS/GR, 256>>>(gamma);
    finalize_k<<<1, 256>>>(gamma, beta);
    out_k<<<dim3(NN/32, CO/32, BB), dim3(32, 8)>>>(out);
}